// round 1
// baseline (speedup 1.0000x reference)
#include <cuda_runtime.h>
#include <cstddef>

#define G      8192
#define BATCH  32
#define O      128
#define TG     64
#define BK     16
#define GT     (G / TG)            // 128 g-tiles
#define NBLK   (BATCH * GT)        // 4096 gemm blocks
#define EPSV   1e-5f
#define SLOPE  0.1f

// ---------------- device scratch (no allocations allowed) ----------------
__device__ float d_Y0[(size_t)BATCH * O * G];
__device__ float d_Y1[(size_t)BATCH * O * G];
__device__ float d_Psum[(size_t)O * NBLK];
__device__ float d_Psq [(size_t)O * NBLK];
__device__ float d_WeffT[O * O];      // [c][o]  (c up to 128)
__device__ float d_Wev[3 * O];        // [j][o]
__device__ float d_Bias[BATCH * O];   // per-batch x0 bias
__device__ float d_Aa[2 * O];         // ping-pong BN scale
__device__ float d_Cc[2 * O];         // ping-pong BN shift

// ---------------- prep: W_eff^T, W_ev, per-batch bias ----------------
__global__ void prep_kernel(const float* __restrict__ W, int C,
                            const float* __restrict__ Xin,
                            const float* __restrict__ aPrev,
                            const float* __restrict__ cPrev)
{
    int Kw = 2 * C + 3;
    int idx = blockIdx.x * blockDim.x + threadIdx.x;
    int n1 = C * O, n2 = n1 + 3 * O, n3 = n2 + BATCH * O;
    if (idx < n1) {
        int c = idx >> 7, o = idx & 127;
        d_WeffT[idx] = W[o * Kw + c] + W[o * Kw + C + c];
    } else if (idx < n2) {
        int r = idx - n1; int j = r >> 7, o = r & 127;
        d_Wev[r] = W[o * Kw + 2 * C + j];
    } else if (idx < n3) {
        int r = idx - n2; int b = r >> 7, o = r & 127;
        float acc = 0.f;
        const float* xp = Xin + (size_t)b * C * G;
        for (int c = 0; c < C; c++) {
            float x = xp[(size_t)c * G];
            if (aPrev) {
                x = fmaf(aPrev[c], x, cPrev[c]);
                x = x >= 0.f ? x : SLOPE * x;
            }
            acc = fmaf(W[o * Kw + C + c], x, acc);
        }
        d_Bias[r] = acc;
    }
}

// ---------------- main GEMM (+ fused input BN/leaky, + stats partials) ----------------
__global__ void __launch_bounds__(256, 2)
gemm_kernel(const float* __restrict__ Xin, int Cin,
            const float* __restrict__ ev,
            const float* __restrict__ aPrev,
            const float* __restrict__ cPrev,
            float* __restrict__ Yout)
{
    __shared__ __align__(16) float Ws[BK][O];
    __shared__ __align__(16) float Xs[BK][TG];
    __shared__ __align__(16) float sWev[3][O];
    __shared__ __align__(16) float sEv[3][TG];
    __shared__ float red[O][17];

    int gt = blockIdx.x, b = blockIdx.y;
    int blin = b * GT + gt;
    int g0 = gt * TG;
    int tid = threadIdx.x;
    int tx = tid & 15, ty = tid >> 4;

    float acc[8][4];
#pragma unroll
    for (int i = 0; i < 8; i++)
#pragma unroll
        for (int j = 0; j < 4; j++) acc[i][j] = 0.f;

    const float* xb = Xin + (size_t)b * Cin * G + g0;

    for (int kt = 0; kt < Cin; kt += BK) {
#pragma unroll
        for (int i = 0; i < 8; i++) {          // BK*128 weights, 8/thread
            int e = tid + i * 256;
            int k = e >> 7, o = e & 127;
            Ws[k][o] = d_WeffT[(kt + k) * O + o];
        }
#pragma unroll
        for (int i = 0; i < 4; i++) {          // BK*64 inputs, 4/thread
            int e = tid + i * 256;
            int k = e >> 6, g = e & 63;
            float x = xb[(size_t)(kt + k) * G + g];
            if (aPrev) {
                x = fmaf(aPrev[kt + k], x, cPrev[kt + k]);
                x = x >= 0.f ? x : SLOPE * x;
            }
            Xs[k][g] = x;
        }
        __syncthreads();
#pragma unroll
        for (int k = 0; k < BK; k++) {
            float4 wa = *(const float4*)&Ws[k][ty * 8];
            float4 wb = *(const float4*)&Ws[k][ty * 8 + 4];
            float4 xv = *(const float4*)&Xs[k][tx * 4];
            float wf[8] = {wa.x, wa.y, wa.z, wa.w, wb.x, wb.y, wb.z, wb.w};
            float xf[4] = {xv.x, xv.y, xv.z, xv.w};
#pragma unroll
            for (int i = 0; i < 8; i++)
#pragma unroll
                for (int j = 0; j < 4; j++)
                    acc[i][j] = fmaf(wf[i], xf[j], acc[i][j]);
        }
        __syncthreads();
    }

    // edge-vector contribution (3 extra K rows)
    for (int e = tid; e < 3 * O; e += 256) sWev[e >> 7][e & 127] = d_Wev[e];
    if (tid < 3 * TG) {
        int j = tid / TG, g = tid % TG;
        sEv[j][g] = ev[(size_t)b * 3 * G + (size_t)j * G + g0 + g];
    }
    __syncthreads();
#pragma unroll
    for (int j3 = 0; j3 < 3; j3++) {
        float wf[8], xf[4];
#pragma unroll
        for (int i = 0; i < 8; i++) wf[i] = sWev[j3][ty * 8 + i];
#pragma unroll
        for (int j = 0; j < 4; j++) xf[j] = sEv[j3][tx * 4 + j];
#pragma unroll
        for (int i = 0; i < 8; i++)
#pragma unroll
            for (int j = 0; j < 4; j++)
                acc[i][j] = fmaf(wf[i], xf[j], acc[i][j]);
    }

    // subtract per-batch x0 bias, write tile, gather local stats
    float ls[8], lq[8];
#pragma unroll
    for (int i = 0; i < 8; i++) {
        int o = ty * 8 + i;
        float bv = d_Bias[b * O + o];
#pragma unroll
        for (int j = 0; j < 4; j++) acc[i][j] -= bv;
        float4 v = make_float4(acc[i][0], acc[i][1], acc[i][2], acc[i][3]);
        *(float4*)(Yout + (size_t)b * O * G + (size_t)o * G + g0 + tx * 4) = v;
        ls[i] = acc[i][0] + acc[i][1] + acc[i][2] + acc[i][3];
        lq[i] = acc[i][0] * acc[i][0] + acc[i][1] * acc[i][1]
              + acc[i][2] * acc[i][2] + acc[i][3] * acc[i][3];
    }

    // deterministic per-block channel partials
    __syncthreads();
#pragma unroll
    for (int i = 0; i < 8; i++) red[ty * 8 + i][tx] = ls[i];
    __syncthreads();
    if (tid < O) {
        float s = 0.f;
#pragma unroll
        for (int t = 0; t < 16; t++) s += red[tid][t];
        d_Psum[(size_t)tid * NBLK + blin] = s;
    }
    __syncthreads();
#pragma unroll
    for (int i = 0; i < 8; i++) red[ty * 8 + i][tx] = lq[i];
    __syncthreads();
    if (tid < O) {
        float s = 0.f;
#pragma unroll
        for (int t = 0; t < 16; t++) s += red[tid][t];
        d_Psq[(size_t)tid * NBLK + blin] = s;
    }
}

// ---------------- stats: reduce partials -> affine (a, c) ----------------
__global__ void stats_kernel(const float* __restrict__ gamma,
                             const float* __restrict__ beta,
                             float* __restrict__ aOut,
                             float* __restrict__ cOut)
{
    int o = blockIdx.x;
    int tid = threadIdx.x;
    float s = 0.f, q = 0.f;
    for (int i = tid; i < NBLK; i += 256) {
        s += d_Psum[(size_t)o * NBLK + i];
        q += d_Psq [(size_t)o * NBLK + i];
    }
    __shared__ float ss[256], sq[256];
    ss[tid] = s; sq[tid] = q;
    __syncthreads();
    for (int st = 128; st > 0; st >>= 1) {
        if (tid < st) { ss[tid] += ss[tid + st]; sq[tid] += sq[tid + st]; }
        __syncthreads();
    }
    if (tid == 0) {
        float N = (float)((size_t)BATCH * G);
        float m = ss[0] / N;
        float v = sq[0] / N - m * m;
        float inv = rsqrtf(v + EPSV);
        float a = gamma[o] * inv;
        aOut[o] = a;
        cOut[o] = beta[o] - a * m;
    }
}

// ---------------- final: fused BN + leaky + max over G ----------------
__global__ void final_kernel(const float* __restrict__ Y,
                             const float* __restrict__ a,
                             const float* __restrict__ c,
                             float* __restrict__ out)
{
    int row = blockIdx.x;          // b*128 + o
    int o = row & 127;
    int tid = threadIdx.x;
    float av = a[o], cv = c[o];
    float m = -3.4e38f;
    const float* p = Y + (size_t)row * G;
    for (int g = tid; g < G; g += 256) {
        float v = fmaf(av, p[g], cv);
        v = v >= 0.f ? v : SLOPE * v;
        m = fmaxf(m, v);
    }
    __shared__ float sm[256];
    sm[tid] = m;
    __syncthreads();
    for (int st = 128; st > 0; st >>= 1) {
        if (tid < st) sm[tid] = fmaxf(sm[tid], sm[tid + st]);
        __syncthreads();
    }
    if (tid == 0) out[row] = sm[0];
}

// ---------------- launcher ----------------
extern "C" void kernel_launch(void* const* d_in, const int* in_sizes, int n_in,
                              void* d_out, int out_size)
{
    const float* feat = (const float*)d_in[0];
    const float* ev   = (const float*)d_in[1];
    const float* W[4] = {(const float*)d_in[2], (const float*)d_in[3],
                         (const float*)d_in[4], (const float*)d_in[5]};
    const float* gm[4] = {(const float*)d_in[6],  (const float*)d_in[8],
                          (const float*)d_in[10], (const float*)d_in[12]};
    const float* bt[4] = {(const float*)d_in[7],  (const float*)d_in[9],
                          (const float*)d_in[11], (const float*)d_in[13]};
    float* out = (float*)d_out;

    float *y0, *y1, *aa, *cc;
    cudaGetSymbolAddress((void**)&y0, d_Y0);
    cudaGetSymbolAddress((void**)&y1, d_Y1);
    cudaGetSymbolAddress((void**)&aa, d_Aa);
    cudaGetSymbolAddress((void**)&cc, d_Cc);

    dim3 gg(GT, BATCH);
    float* ybuf[2] = {y0, y1};
    const float* cur = feat;
    int curC = 64;
    float* aPrev = nullptr;
    float* cPrev = nullptr;

    for (int L = 0; L < 4; L++) {
        int dst = L & 1;               // L0->y0, L1->y1, L2->y0, L3->y1
        float* aCur = aa + dst * O;
        float* cCur = cc + dst * O;
        int prepN = curC * O + 3 * O + BATCH * O;
        prep_kernel<<<(prepN + 255) / 256, 256>>>(W[L], curC, cur, aPrev, cPrev);
        gemm_kernel<<<gg, 256>>>(cur, curC, ev, aPrev, cPrev, ybuf[dst]);
        stats_kernel<<<O, 256>>>(gm[L], bt[L], aCur, cCur);
        cur = ybuf[dst];
        curC = O;
        aPrev = aCur;
        cPrev = cCur;
    }
    final_kernel<<<BATCH * O, 256>>>(cur, aPrev, cPrev, out);
}

// round 3
// speedup vs baseline: 1.3918x; 1.3918x over previous
#include <cuda_runtime.h>
#include <cuda_fp16.h>
#include <cstdint>
#include <cstddef>

#define GPTS   8192
#define NBATCH 32
#define OCH    128
#define TN     128
#define NTILE  (GPTS / TN)          // 64 g-tiles
#define NB     (NBATCH * NTILE)     // 2048 CTAs per layer
#define KSEC   32
#define EPSV   1e-5f
#define SLOPE  0.1f

// SMEM byte offsets (dynamic)
#define SMB_BUF    0        // 2 x 32KB: [Wh 8K | Wl 8K | Xh 8K | Xl 8K]
#define SMB_YS     0        // epilogue alias: 128 x 132 floats = 67584
#define SMB_AF     68608    // affine a[128], c[128]
#define SMB_ST     69632    // stats staging 512 floats
#define SMB_DYN    71680

// ---------------- device scratch ----------------
__device__ float d_Y0[(size_t)NBATCH * OCH * GPTS];
__device__ float d_Y1[(size_t)NBATCH * OCH * GPTS];
__device__ float d_Psum[(size_t)OCH * NB];
__device__ float d_Psq [(size_t)OCH * NB];
__device__ __half d_Whi[OCH * 192];
__device__ __half d_Wlo[OCH * 192];
__device__ float d_X0[NBATCH * OCH];
__device__ float d_Bias[NBATCH * OCH];
__device__ float d_Aa[2 * OCH];
__device__ float d_Cc[2 * OCH];

// ---------------- helpers ----------------
__device__ __forceinline__ uint32_t smem_u32(const void* p) {
    uint32_t a;
    asm("{ .reg .u64 t; cvta.to.shared.u64 t, %1; cvt.u32.u64 %0, t; }" : "=r"(a) : "l"(p));
    return a;
}
__device__ __forceinline__ void ldsm4(uint32_t* r, uint32_t addr) {
    asm volatile("ldmatrix.sync.aligned.m8n8.x4.shared.b16 {%0,%1,%2,%3}, [%4];"
        : "=r"(r[0]), "=r"(r[1]), "=r"(r[2]), "=r"(r[3]) : "r"(addr));
}
__device__ __forceinline__ void mma16816(float* c, const uint32_t* a, const uint32_t* b) {
    asm volatile("mma.sync.aligned.m16n8k16.row.col.f32.f16.f16.f32 "
        "{%0,%1,%2,%3}, {%4,%5,%6,%7}, {%8,%9}, {%0,%1,%2,%3};"
        : "+f"(c[0]), "+f"(c[1]), "+f"(c[2]), "+f"(c[3])
        : "r"(a[0]), "r"(a[1]), "r"(a[2]), "r"(a[3]), "r"(b[0]), "r"(b[1]));
}
// swizzled byte offset of halfword column kc (0..31) in row `row` (64B rows)
__device__ __forceinline__ uint32_t swz_off(int row, int kc) {
    return (uint32_t)(row * 64 + ((((kc >> 3) ^ ((row >> 1) & 3)) << 4)) + (kc & 7) * 2);
}

// ---------------- prep: fold weights, split fp16 hi/lo, x0 column ----------------
__global__ void prep_w(const float* __restrict__ W, int Cin,
                       const float* __restrict__ X,
                       const float* __restrict__ aP, const float* __restrict__ cP)
{
    int Kw = 2 * Cin + 3;
    int idx = blockIdx.x * blockDim.x + threadIdx.x;
    if (idx < OCH * 192) {
        int o = idx / 192, c = idx % 192;
        float v = 0.f;
        if (c < Cin)          v = W[o * Kw + c] + W[o * Kw + Cin + c];
        else if (c < Cin + 3) v = W[o * Kw + 2 * Cin + (c - Cin)];
        __half h = __float2half_rn(v);
        d_Whi[idx] = h;
        d_Wlo[idx] = __float2half_rn(v - __half2float(h));
    } else {
        int r = idx - OCH * 192;
        if (r < NBATCH * Cin) {
            int b = r / Cin, ch = r % Cin;
            float x = X[(size_t)b * Cin * GPTS + (size_t)ch * GPTS];
            if (aP) { x = fmaf(aP[ch], x, cP[ch]); x = x >= 0.f ? x : SLOPE * x; }
            d_X0[b * OCH + ch] = x;
        }
    }
}

__global__ void prep_bias(const float* __restrict__ W, int Cin)
{
    __shared__ float x0[OCH];
    int b = blockIdx.x, o = threadIdx.x;
    if (o < Cin) x0[o] = d_X0[b * OCH + o];
    __syncthreads();
    int Kw = 2 * Cin + 3;
    float acc = 0.f;
    for (int c = 0; c < Cin; c++) acc = fmaf(W[o * Kw + Cin + c], x0[c], acc);
    d_Bias[b * OCH + o] = acc;
}

// ---------------- HMMA GEMM layer ----------------
__global__ void __launch_bounds__(256, 1)
gemm_mm(const float* __restrict__ X, int Cin, int nsec,
        const float* __restrict__ ev,
        const float* __restrict__ aP, const float* __restrict__ cP,
        float* __restrict__ Y)
{
    extern __shared__ __align__(16) char smem[];
    uint32_t sb = smem_u32(smem);

    const int tid = threadIdx.x, lane = tid & 31, wid = tid >> 5;
    const int wm = wid >> 2, wn = wid & 3;
    const int gt = blockIdx.x, b = blockIdx.y;
    const int g0 = gt * TN;
    const int ctaIdx = b * NTILE + gt;
    const bool useAff = (aP != nullptr);

    // affine coefficients to smem
    float* afp = (float*)(smem + SMB_AF);
    if (tid < OCH) { afp[tid] = useAff ? aP[tid] : 1.f; afp[OCH + tid] = useAff ? cP[tid] : 0.f; }
    __syncthreads();

    const float* xb  = X  + (size_t)b * Cin * GPTS + g0;
    const float* evb = ev + (size_t)b * 3   * GPTS + g0;
    const uint32_t* Wh32 = (const uint32_t*)d_Whi;
    const uint32_t* Wl32 = (const uint32_t*)d_Wlo;

    // loader roles: g = tid&127, chh = tid>>7 selects 16-channel half of the section
    const int lg = tid & 127, chh = tid >> 7;

    float    xr[16];
    uint32_t wh[8], wl[8];

    float c[4][4][4];
#pragma unroll
    for (int mi = 0; mi < 4; mi++)
#pragma unroll
        for (int ni = 0; ni < 4; ni++)
#pragma unroll
            for (int e = 0; e < 4; e++) c[mi][ni][e] = 0.f;

    // ldg stage -> regs
    auto ldg_stage = [&](int s) {
#pragma unroll
        for (int j = 0; j < 16; j++) {
            int ch = s * KSEC + chh * 16 + j;
            float v = 0.f;
            if (ch < Cin)            v = xb[(size_t)ch * GPTS + lg];
            else if (ch < Cin + 3)   v = evb[(size_t)(ch - Cin) * GPTS + lg];
            xr[j] = v;
        }
#pragma unroll
        for (int i = 0; i < 8; i++) {
            int idx = tid + i * 256;                  // 0..2047
            int o = idx >> 4, kp = idx & 15;
            wh[i] = Wh32[o * 96 + s * 16 + kp];
            wl[i] = Wl32[o * 96 + s * 16 + kp];
        }
    };
    // regs -> smem (with affine + leaky + fp16 split)
    auto sts_stage = [&](int s, int buf) {
        uint32_t WhB = sb + SMB_BUF + buf * 32768;
        uint32_t WlB = WhB + 8192;
        uint32_t XhB = WhB + 16384;
        uint32_t XlB = WhB + 24576;
#pragma unroll
        for (int j2 = 0; j2 < 8; j2++) {
            int kc = chh * 16 + j2 * 2;               // section-local half column
            int ch0 = s * KSEC + kc;
            float v0 = xr[j2 * 2], v1 = xr[j2 * 2 + 1];
            if (useAff) {
                if (ch0 < Cin)     { v0 = fmaf(afp[ch0], v0, afp[OCH + ch0]); v0 = v0 >= 0.f ? v0 : SLOPE * v0; }
                if (ch0 + 1 < Cin) { v1 = fmaf(afp[ch0 + 1], v1, afp[OCH + ch0 + 1]); v1 = v1 >= 0.f ? v1 : SLOPE * v1; }
            }
            __half h0 = __float2half_rn(v0), h1 = __float2half_rn(v1);
            __half l0 = __float2half_rn(v0 - __half2float(h0));
            __half l1 = __float2half_rn(v1 - __half2float(h1));
            __half2 hp = __halves2half2(h0, h1), lp = __halves2half2(l0, l1);
            uint32_t off = swz_off(lg, kc);
            *(uint32_t*)(smem + (XhB - sb) + off) = *(uint32_t*)&hp;
            *(uint32_t*)(smem + (XlB - sb) + off) = *(uint32_t*)&lp;
        }
#pragma unroll
        for (int i = 0; i < 8; i++) {
            int idx = tid + i * 256;
            int o = idx >> 4, kc = (idx & 15) * 2;
            uint32_t off = swz_off(o, kc);
            *(uint32_t*)(smem + (WhB - sb) + off) = wh[i];
            *(uint32_t*)(smem + (WlB - sb) + off) = wl[i];
        }
    };

    ldg_stage(0);
    sts_stage(0, 0);

    for (int s = 0; s < nsec; s++) {
        int buf = s & 1;
        if (s + 1 < nsec) ldg_stage(s + 1);
        __syncthreads();                              // buf ready for all
        uint32_t WhB = sb + SMB_BUF + buf * 32768;
        uint32_t WlB = WhB + 8192;
        uint32_t XhB = WhB + 16384;
        uint32_t XlB = WhB + 24576;
#pragma unroll
        for (int ks = 0; ks < 2; ks++) {
            uint32_t ah[4][4], al[4][4], bh[4][2], bl[4][2];
#pragma unroll
            for (int mi = 0; mi < 4; mi++) {
                int row = wm * 64 + mi * 16 + (lane & 15);
                int chunk = 2 * ks + (lane >> 4);
                uint32_t off = (uint32_t)(row * 64 + (((chunk ^ ((row >> 1) & 3)) << 4)));
                ldsm4(ah[mi], WhB + off);
                ldsm4(al[mi], WlB + off);
            }
#pragma unroll
            for (int p = 0; p < 2; p++) {
                int row = wn * 32 + p * 16 + (lane & 7) + ((lane >> 4) << 3);
                int chunk = 2 * ks + ((lane >> 3) & 1);
                uint32_t off = (uint32_t)(row * 64 + (((chunk ^ ((row >> 1) & 3)) << 4)));
                uint32_t t[4];
                ldsm4(t, XhB + off);
                bh[2 * p][0] = t[0]; bh[2 * p][1] = t[1];
                bh[2 * p + 1][0] = t[2]; bh[2 * p + 1][1] = t[3];
                ldsm4(t, XlB + off);
                bl[2 * p][0] = t[0]; bl[2 * p][1] = t[1];
                bl[2 * p + 1][0] = t[2]; bl[2 * p + 1][1] = t[3];
            }
#pragma unroll
            for (int mi = 0; mi < 4; mi++)
#pragma unroll
                for (int ni = 0; ni < 4; ni++) {
                    mma16816(c[mi][ni], ah[mi], bh[ni]);
                    mma16816(c[mi][ni], ah[mi], bl[ni]);
                    mma16816(c[mi][ni], al[mi], bh[ni]);
                }
        }
        if (s + 1 < nsec) sts_stage(s + 1, buf ^ 1);
        __syncthreads();                              // protect buf reuse
    }

    // ---------------- epilogue: stage, bias, stats, store ----------------
    float* Ysm = (float*)(smem + SMB_YS);
#pragma unroll
    for (int mi = 0; mi < 4; mi++)
#pragma unroll
        for (int ni = 0; ni < 4; ni++) {
            int r0 = wm * 64 + mi * 16 + (lane >> 2);
            int cc = wn * 32 + ni * 8 + 2 * (lane & 3);
            Ysm[r0 * 132 + cc]           = c[mi][ni][0];
            Ysm[r0 * 132 + cc + 1]       = c[mi][ni][1];
            Ysm[(r0 + 8) * 132 + cc]     = c[mi][ni][2];
            Ysm[(r0 + 8) * 132 + cc + 1] = c[mi][ni][3];
        }
    __syncthreads();

    int o = tid >> 1, hc = tid & 1;
    float bias = d_Bias[b * OCH + o];
    float s1 = 0.f, s2 = 0.f;
    float* yrow = Y + ((size_t)b * OCH + o) * GPTS + g0 + hc * 64;
    const float* yr = &Ysm[o * 132 + hc * 64];
#pragma unroll
    for (int j = 0; j < 64; j += 4) {
        float4 v;
        v.x = yr[j]     - bias;
        v.y = yr[j + 1] - bias;
        v.z = yr[j + 2] - bias;
        v.w = yr[j + 3] - bias;
        s1 += (v.x + v.y) + (v.z + v.w);
        s2 += (v.x * v.x + v.y * v.y) + (v.z * v.z + v.w * v.w);
        *(float4*)(yrow + j) = v;
    }
    float* st = (float*)(smem + SMB_ST);
    st[o * 2 + hc] = s1;
    st[256 + o * 2 + hc] = s2;
    __syncthreads();
    if (tid < OCH) {
        d_Psum[(size_t)tid * NB + ctaIdx] = st[tid * 2] + st[tid * 2 + 1];
        d_Psq [(size_t)tid * NB + ctaIdx] = st[256 + tid * 2] + st[256 + tid * 2 + 1];
    }
}

// ---------------- stats ----------------
__global__ void stats_kernel(const float* __restrict__ gamma,
                             const float* __restrict__ beta,
                             float* __restrict__ aOut, float* __restrict__ cOut)
{
    int o = blockIdx.x, tid = threadIdx.x;
    float s = 0.f, q = 0.f;
    for (int i = tid; i < NB; i += 256) {
        s += d_Psum[(size_t)o * NB + i];
        q += d_Psq [(size_t)o * NB + i];
    }
    __shared__ float ss[256], sq[256];
    ss[tid] = s; sq[tid] = q;
    __syncthreads();
    for (int st = 128; st > 0; st >>= 1) {
        if (tid < st) { ss[tid] += ss[tid + st]; sq[tid] += sq[tid + st]; }
        __syncthreads();
    }
    if (tid == 0) {
        float N = (float)((size_t)NBATCH * GPTS);
        float m = ss[0] / N;
        float v = sq[0] / N - m * m;
        float inv = rsqrtf(v + EPSV);
        float a = gamma[o] * inv;
        aOut[o] = a;
        cOut[o] = beta[o] - a * m;
    }
}

// ---------------- final: BN + leaky + max over G ----------------
__global__ void final_kernel(const float* __restrict__ Y,
                             const float* __restrict__ a,
                             const float* __restrict__ c,
                             float* __restrict__ out)
{
    int row = blockIdx.x;
    int o = row & 127;
    int tid = threadIdx.x;
    float av = a[o], cv = c[o];
    float m = -3.4e38f;
    const float* p = Y + (size_t)row * GPTS;
    for (int g = tid; g < GPTS; g += 256) {
        float v = fmaf(av, p[g], cv);
        v = v >= 0.f ? v : SLOPE * v;
        m = fmaxf(m, v);
    }
    __shared__ float smx[256];
    smx[tid] = m;
    __syncthreads();
    for (int st = 128; st > 0; st >>= 1) {
        if (tid < st) smx[tid] = fmaxf(smx[tid], smx[tid + st]);
        __syncthreads();
    }
    if (tid == 0) out[row] = smx[0];
}

// ---------------- launcher ----------------
extern "C" void kernel_launch(void* const* d_in, const int* in_sizes, int n_in,
                              void* d_out, int out_size)
{
    const float* feat = (const float*)d_in[0];
    const float* ev   = (const float*)d_in[1];
    const float* W[4] = {(const float*)d_in[2], (const float*)d_in[3],
                         (const float*)d_in[4], (const float*)d_in[5]};
    const float* gm[4] = {(const float*)d_in[6],  (const float*)d_in[8],
                          (const float*)d_in[10], (const float*)d_in[12]};
    const float* bt[4] = {(const float*)d_in[7],  (const float*)d_in[9],
                          (const float*)d_in[11], (const float*)d_in[13]};
    float* out = (float*)d_out;

    cudaFuncSetAttribute(gemm_mm, cudaFuncAttributeMaxDynamicSharedMemorySize, SMB_DYN);

    float *y0, *y1, *aa, *cc;
    cudaGetSymbolAddress((void**)&y0, d_Y0);
    cudaGetSymbolAddress((void**)&y1, d_Y1);
    cudaGetSymbolAddress((void**)&aa, d_Aa);
    cudaGetSymbolAddress((void**)&cc, d_Cc);

    float* ybuf[2] = {y0, y1};
    const float* cur = feat;
    int curC = 64;
    float* aPrev = nullptr;
    float* cPrev = nullptr;

    dim3 gg(NTILE, NBATCH);
    for (int L = 0; L < 4; L++) {
        int dst = L & 1;
        float* aCur = aa + dst * OCH;
        float* cCur = cc + dst * OCH;
        int nsec = (curC + 3 + KSEC - 1) / KSEC;      // 64->3, 128->5
        int prepN = OCH * 192 + NBATCH * curC;
        prep_w<<<(prepN + 255) / 256, 256>>>(W[L], curC, cur, aPrev, cPrev);
        prep_bias<<<NBATCH, OCH>>>(W[L], curC);
        gemm_mm<<<gg, 256, SMB_DYN>>>(cur, curC, nsec, ev, aPrev, cPrev, ybuf[dst]);
        stats_kernel<<<OCH, 256>>>(gm[L], bt[L], aCur, cCur);
        cur = ybuf[dst];
        curC = OCH;
        aPrev = aCur;
        cPrev = cCur;
    }
    final_kernel<<<NBATCH * OCH, 256>>>(cur, aPrev, cPrev, out);
}

// round 4
// speedup vs baseline: 1.7304x; 1.2433x over previous
#include <cuda_runtime.h>
#include <cuda_fp16.h>
#include <cstdint>
#include <cstddef>

#define GPTS   8192
#define NBATCH 32
#define OCH    128
#define TN     128
#define NTILE  (GPTS / TN)          // 64 g-tiles
#define NB     (NBATCH * NTILE)     // 2048 CTAs per layer
#define KSEC   32
#define EPSV   1e-5f
#define SLOPE  0.1f

// SMEM byte offsets (dynamic)
#define SMB_BUF    0        // 2 x 32KB: [Wh 8K | Wl 8K | Xh 8K | Xl 8K]
#define SMB_YS     0        // epilogue alias: 128 x 132 floats = 67584
#define SMB_AF     68608    // affine a[128], c[128]
#define SMB_ST     69632    // stats staging 512 floats
#define SMB_DYN    71680

// ---------------- device scratch ----------------
__device__ float d_Y0[(size_t)NBATCH * OCH * GPTS];
__device__ float d_Y1[(size_t)NBATCH * OCH * GPTS];
__device__ float d_Psum[(size_t)OCH * NB];
__device__ float d_Psq [(size_t)OCH * NB];
__device__ __half d_Whi[OCH * 192];
__device__ __half d_Wlo[OCH * 192];
__device__ float d_Bias[NBATCH * OCH];
__device__ float d_Aa[2 * OCH];
__device__ float d_Cc[2 * OCH];

// ---------------- helpers ----------------
__device__ __forceinline__ uint32_t smem_u32(const void* p) {
    uint32_t a;
    asm("{ .reg .u64 t; cvta.to.shared.u64 t, %1; cvt.u32.u64 %0, t; }" : "=r"(a) : "l"(p));
    return a;
}
__device__ __forceinline__ void ldsm4(uint32_t* r, uint32_t addr) {
    asm volatile("ldmatrix.sync.aligned.m8n8.x4.shared.b16 {%0,%1,%2,%3}, [%4];"
        : "=r"(r[0]), "=r"(r[1]), "=r"(r[2]), "=r"(r[3]) : "r"(addr));
}
__device__ __forceinline__ void mma16816(float* c, const uint32_t* a, const uint32_t* b) {
    asm volatile("mma.sync.aligned.m16n8k16.row.col.f32.f16.f16.f32 "
        "{%0,%1,%2,%3}, {%4,%5,%6,%7}, {%8,%9}, {%0,%1,%2,%3};"
        : "+f"(c[0]), "+f"(c[1]), "+f"(c[2]), "+f"(c[3])
        : "r"(a[0]), "r"(a[1]), "r"(a[2]), "r"(a[3]), "r"(b[0]), "r"(b[1]));
}
__device__ __forceinline__ uint32_t swz_off(int row, int kc) {
    return (uint32_t)(row * 64 + ((((kc >> 3) ^ ((row >> 1) & 3)) << 4)) + (kc & 7) * 2);
}
__device__ __forceinline__ float leaky(float v) { return fmaxf(v, SLOPE * v); }

// ---------------- prep: fold weights, split fp16 hi/lo ----------------
__global__ void prep_w(const float* __restrict__ W, int Cin)
{
    int Kw = 2 * Cin + 3;
    int idx = blockIdx.x * blockDim.x + threadIdx.x;
    if (idx < OCH * 192) {
        int o = idx / 192, c = idx % 192;
        float v = 0.f;
        if (c < Cin)          v = W[o * Kw + c] + W[o * Kw + Cin + c];
        else if (c < Cin + 3) v = W[o * Kw + 2 * Cin + (c - Cin)];
        __half h = __float2half_rn(v);
        d_Whi[idx] = h;
        d_Wlo[idx] = __float2half_rn(v - __half2float(h));
    }
}

// ---------------- prep: per-batch x0 bias ----------------
__global__ void prep_bias(const float* __restrict__ W, int Cin,
                          const float* __restrict__ X,
                          const float* __restrict__ aP, const float* __restrict__ cP)
{
    __shared__ float x0[OCH];
    int b = blockIdx.x, o = threadIdx.x;
    if (o < Cin) {
        float x = X[(size_t)b * Cin * GPTS + (size_t)o * GPTS];
        if (aP) x = leaky(fmaf(aP[o], x, cP[o]));
        x0[o] = x;
    }
    __syncthreads();
    int Kw = 2 * Cin + 3;
    float acc = 0.f;
    for (int c = 0; c < Cin; c++) acc = fmaf(W[o * Kw + Cin + c], x0[c], acc);
    d_Bias[b * OCH + o] = acc;
}

// ---------------- HMMA GEMM layer ----------------
__global__ void __launch_bounds__(256, 2)
gemm_mm(const float* __restrict__ X, int Cin, int nsec,
        const float* __restrict__ ev,
        const float* __restrict__ aP, const float* __restrict__ cP,
        float* __restrict__ Y)
{
    extern __shared__ __align__(16) char smem[];
    uint32_t sb = smem_u32(smem);

    const int tid = threadIdx.x, lane = tid & 31, wid = tid >> 5;
    const int wm = wid >> 2, wn = wid & 3;
    const int gt = blockIdx.x, b = blockIdx.y;
    const int g0 = gt * TN;
    const int ctaIdx = b * NTILE + gt;
    const bool useAff = (aP != nullptr);

    float* afp = (float*)(smem + SMB_AF);
    if (tid < OCH) { afp[tid] = useAff ? aP[tid] : 1.f; afp[OCH + tid] = useAff ? cP[tid] : 0.f; }
    __syncthreads();

    const float* xb  = X  + (size_t)b * Cin * GPTS + g0;
    const float* evb = ev + (size_t)b * 3   * GPTS + g0;
    const uint32_t* Wh32 = (const uint32_t*)d_Whi;
    const uint32_t* Wl32 = (const uint32_t*)d_Wlo;

    const int lg = tid & 127, chh = tid >> 7;

    float xr[16];

    float c[4][4][4];
#pragma unroll
    for (int mi = 0; mi < 4; mi++)
#pragma unroll
        for (int ni = 0; ni < 4; ni++)
#pragma unroll
            for (int e = 0; e < 4; e++) c[mi][ni][e] = 0.f;

    auto ldgX = [&](int s) {
#pragma unroll
        for (int j = 0; j < 16; j++) {
            int ch = s * KSEC + chh * 16 + j;
            float v = 0.f;
            if (ch < Cin)            v = xb[(size_t)ch * GPTS + lg];
            else if (ch < Cin + 3)   v = evb[(size_t)(ch - Cin) * GPTS + lg];
            xr[j] = v;
        }
    };
    auto stsX = [&](int s, int buf) {
        uint32_t XhO = SMB_BUF + buf * 32768 + 16384;
        uint32_t XlO = XhO + 8192;
#pragma unroll
        for (int j2 = 0; j2 < 8; j2++) {
            int kc = chh * 16 + j2 * 2;
            int ch0 = s * KSEC + kc;
            float v0 = xr[j2 * 2], v1 = xr[j2 * 2 + 1];
            if (useAff) {
                if (ch0 < Cin)     v0 = leaky(fmaf(afp[ch0], v0, afp[OCH + ch0]));
                if (ch0 + 1 < Cin) v1 = leaky(fmaf(afp[ch0 + 1], v1, afp[OCH + ch0 + 1]));
            }
            __half h0 = __float2half_rn(v0), h1 = __float2half_rn(v1);
            __half l0 = __float2half_rn(v0 - __half2float(h0));
            __half l1 = __float2half_rn(v1 - __half2float(h1));
            __half2 hp = __halves2half2(h0, h1), lp = __halves2half2(l0, l1);
            uint32_t off = swz_off(lg, kc);
            *(uint32_t*)(smem + XhO + off) = *(uint32_t*)&hp;
            *(uint32_t*)(smem + XlO + off) = *(uint32_t*)&lp;
        }
    };
    auto stsW = [&](int s, int buf) {
        uint32_t WhO = SMB_BUF + buf * 32768;
        uint32_t WlO = WhO + 8192;
#pragma unroll
        for (int i = 0; i < 8; i++) {
            int idx = tid + i * 256;
            int o = idx >> 4, kp = idx & 15;
            uint32_t vh = Wh32[o * 96 + s * 16 + kp];
            uint32_t vl = Wl32[o * 96 + s * 16 + kp];
            uint32_t off = swz_off(o, kp * 2);
            *(uint32_t*)(smem + WhO + off) = vh;
            *(uint32_t*)(smem + WlO + off) = vl;
        }
    };

    // prologue: fill buffer 0
    ldgX(0);
    stsX(0, 0);
    stsW(0, 0);

    for (int s = 0; s < nsec; s++) {
        int buf = s & 1;
        __syncthreads();                      // buf[s&1] visible; buf[s^1] free
        if (s + 1 < nsec) ldgX(s + 1);        // issue global loads early

        uint32_t WhB = sb + SMB_BUF + buf * 32768;
        uint32_t WlB = WhB + 8192;
        uint32_t XhB = WhB + 16384;
        uint32_t XlB = WhB + 24576;
#pragma unroll
        for (int ks = 0; ks < 2; ks++) {
            uint32_t ah[4][4], bh[4][2], bl[4][2];
#pragma unroll
            for (int mi = 0; mi < 4; mi++) {
                int row = wm * 64 + mi * 16 + (lane & 15);
                int chunk = 2 * ks + (lane >> 4);
                uint32_t off = (uint32_t)(row * 64 + (((chunk ^ ((row >> 1) & 3)) << 4)));
                ldsm4(ah[mi], WhB + off);
            }
#pragma unroll
            for (int p = 0; p < 2; p++) {
                int row = wn * 32 + p * 16 + (lane & 7) + ((lane >> 4) << 3);
                int chunk = 2 * ks + ((lane >> 3) & 1);
                uint32_t off = (uint32_t)(row * 64 + (((chunk ^ ((row >> 1) & 3)) << 4)));
                uint32_t t[4];
                ldsm4(t, XhB + off);
                bh[2 * p][0] = t[0]; bh[2 * p][1] = t[1];
                bh[2 * p + 1][0] = t[2]; bh[2 * p + 1][1] = t[3];
                ldsm4(t, XlB + off);
                bl[2 * p][0] = t[0]; bl[2 * p][1] = t[1];
                bl[2 * p + 1][0] = t[2]; bl[2 * p + 1][1] = t[3];
            }
            // term-major: hh, hl, then reload A<-lo and lh
#pragma unroll
            for (int mi = 0; mi < 4; mi++)
#pragma unroll
                for (int ni = 0; ni < 4; ni++) mma16816(c[mi][ni], ah[mi], bh[ni]);
#pragma unroll
            for (int mi = 0; mi < 4; mi++)
#pragma unroll
                for (int ni = 0; ni < 4; ni++) mma16816(c[mi][ni], ah[mi], bl[ni]);
#pragma unroll
            for (int mi = 0; mi < 4; mi++) {
                int row = wm * 64 + mi * 16 + (lane & 15);
                int chunk = 2 * ks + (lane >> 4);
                uint32_t off = (uint32_t)(row * 64 + (((chunk ^ ((row >> 1) & 3)) << 4)));
                ldsm4(ah[mi], WlB + off);
            }
#pragma unroll
            for (int mi = 0; mi < 4; mi++)
#pragma unroll
                for (int ni = 0; ni < 4; ni++) mma16816(c[mi][ni], ah[mi], bh[ni]);
        }

        if (s + 1 < nsec) {
            stsX(s + 1, buf ^ 1);
            stsW(s + 1, buf ^ 1);
        }
    }
    __syncthreads();   // all MMAs done before epilogue aliases the buffers

    // ---------------- epilogue: stage, bias, stats, store ----------------
    float* Ysm = (float*)(smem + SMB_YS);
#pragma unroll
    for (int mi = 0; mi < 4; mi++)
#pragma unroll
        for (int ni = 0; ni < 4; ni++) {
            int r0 = wm * 64 + mi * 16 + (lane >> 2);
            int cc = wn * 32 + ni * 8 + 2 * (lane & 3);
            Ysm[r0 * 132 + cc]           = c[mi][ni][0];
            Ysm[r0 * 132 + cc + 1]       = c[mi][ni][1];
            Ysm[(r0 + 8) * 132 + cc]     = c[mi][ni][2];
            Ysm[(r0 + 8) * 132 + cc + 1] = c[mi][ni][3];
        }
    __syncthreads();

    int o = tid >> 1, hc = tid & 1;
    float bias = d_Bias[b * OCH + o];
    float s1 = 0.f, s2 = 0.f;
    float* yrow = Y + ((size_t)b * OCH + o) * GPTS + g0 + hc * 64;
    const float* yr = &Ysm[o * 132 + hc * 64];
#pragma unroll
    for (int j = 0; j < 64; j += 4) {
        float4 v;
        v.x = yr[j]     - bias;
        v.y = yr[j + 1] - bias;
        v.z = yr[j + 2] - bias;
        v.w = yr[j + 3] - bias;
        s1 += (v.x + v.y) + (v.z + v.w);
        s2 += (v.x * v.x + v.y * v.y) + (v.z * v.z + v.w * v.w);
        *(float4*)(yrow + j) = v;
    }
    float* st = (float*)(smem + SMB_ST);
    st[o * 2 + hc] = s1;
    st[256 + o * 2 + hc] = s2;
    __syncthreads();
    if (tid < OCH) {
        d_Psum[(size_t)tid * NB + ctaIdx] = st[tid * 2] + st[tid * 2 + 1];
        d_Psq [(size_t)tid * NB + ctaIdx] = st[256 + tid * 2] + st[256 + tid * 2 + 1];
    }
}

// ---------------- stats ----------------
__global__ void stats_kernel(const float* __restrict__ gamma,
                             const float* __restrict__ beta,
                             float* __restrict__ aOut, float* __restrict__ cOut)
{
    int o = blockIdx.x, tid = threadIdx.x;
    float s = 0.f, q = 0.f;
    for (int i = tid; i < NB; i += 256) {
        s += d_Psum[(size_t)o * NB + i];
        q += d_Psq [(size_t)o * NB + i];
    }
    __shared__ float ss[256], sq[256];
    ss[tid] = s; sq[tid] = q;
    __syncthreads();
    for (int st = 128; st > 0; st >>= 1) {
        if (tid < st) { ss[tid] += ss[tid + st]; sq[tid] += sq[tid + st]; }
        __syncthreads();
    }
    if (tid == 0) {
        float N = (float)((size_t)NBATCH * GPTS);
        float m = ss[0] / N;
        float v = sq[0] / N - m * m;
        float inv = rsqrtf(v + EPSV);
        float a = gamma[o] * inv;
        aOut[o] = a;
        cOut[o] = beta[o] - a * m;
    }
}

// ---------------- final: BN + leaky + max over G ----------------
__global__ void final_kernel(const float* __restrict__ Y,
                             const float* __restrict__ a,
                             const float* __restrict__ c,
                             float* __restrict__ out)
{
    int row = blockIdx.x;
    int o = row & 127;
    int tid = threadIdx.x;
    float av = a[o], cv = c[o];
    float m = -3.4e38f;
    const float* p = Y + (size_t)row * GPTS;
    for (int g = tid; g < GPTS; g += 256) {
        float v = fmaf(av, p[g], cv);
        m = fmaxf(m, leaky(v));
    }
    __shared__ float smx[256];
    smx[tid] = m;
    __syncthreads();
    for (int st = 128; st > 0; st >>= 1) {
        if (tid < st) smx[tid] = fmaxf(smx[tid], smx[tid + st]);
        __syncthreads();
    }
    if (tid == 0) out[row] = smx[0];
}

// ---------------- launcher ----------------
extern "C" void kernel_launch(void* const* d_in, const int* in_sizes, int n_in,
                              void* d_out, int out_size)
{
    const float* feat = (const float*)d_in[0];
    const float* ev   = (const float*)d_in[1];
    const float* W[4] = {(const float*)d_in[2], (const float*)d_in[3],
                         (const float*)d_in[4], (const float*)d_in[5]};
    const float* gm[4] = {(const float*)d_in[6],  (const float*)d_in[8],
                          (const float*)d_in[10], (const float*)d_in[12]};
    const float* bt[4] = {(const float*)d_in[7],  (const float*)d_in[9],
                          (const float*)d_in[11], (const float*)d_in[13]};
    float* out = (float*)d_out;

    cudaFuncSetAttribute(gemm_mm, cudaFuncAttributeMaxDynamicSharedMemorySize, SMB_DYN);

    float *y0, *y1, *aa, *cc;
    cudaGetSymbolAddress((void**)&y0, d_Y0);
    cudaGetSymbolAddress((void**)&y1, d_Y1);
    cudaGetSymbolAddress((void**)&aa, d_Aa);
    cudaGetSymbolAddress((void**)&cc, d_Cc);

    float* ybuf[2] = {y0, y1};
    const float* cur = feat;
    int curC = 64;
    float* aPrev = nullptr;
    float* cPrev = nullptr;

    dim3 gg(NTILE, NBATCH);
    for (int L = 0; L < 4; L++) {
        int dst = L & 1;
        float* aCur = aa + dst * OCH;
        float* cCur = cc + dst * OCH;
        int nsec = (curC + 3 + KSEC - 1) / KSEC;      // 64->3, 128->5
        prep_w<<<(OCH * 192 + 255) / 256, 256>>>(W[L], curC);
        prep_bias<<<NBATCH, OCH>>>(W[L], curC, cur, aPrev, cPrev);
        gemm_mm<<<gg, 256, SMB_DYN>>>(cur, curC, nsec, ev, aPrev, cPrev, ybuf[dst]);
        stats_kernel<<<OCH, 256>>>(gm[L], bt[L], aCur, cCur);
        cur = ybuf[dst];
        curC = OCH;
        aPrev = aCur;
        cPrev = cCur;
    }
    final_kernel<<<NBATCH * OCH, 256>>>(cur, aPrev, cPrev, out);
}

// round 5
// speedup vs baseline: 1.9575x; 1.1312x over previous
#include <cuda_runtime.h>
#include <cuda_fp16.h>
#include <cstdint>
#include <cstddef>

#define GPTS   8192
#define NBATCH 32
#define OCH    128
#define TN     128
#define NTILE  (GPTS / TN)          // 64 g-tiles
#define NB     (NBATCH * NTILE)     // 2048 CTAs per layer
#define KSEC   32
#define EPSV   1e-5f
#define SLOPE  0.1f

// SMEM byte offsets (dynamic)
// buffer: [Wh 8K | Xh 8K | Xl 8K] = 24KB, x2 buffers = 48KB
#define SMB_BUF    0
#define SMB_YS     0        // epilogue alias: 128 x 132 floats = 67584
#define SMB_AF     68608    // affine a[128], c[128]
#define SMB_ST     69632    // stats staging 512 floats
#define SMB_DYN    71680

// ---------------- device scratch ----------------
__device__ float d_Y0[(size_t)NBATCH * OCH * GPTS];
__device__ float d_Y1[(size_t)NBATCH * OCH * GPTS];
__device__ float d_Psum[(size_t)OCH * NB];
__device__ float d_Psq [(size_t)OCH * NB];
__device__ __half d_Whi[OCH * 192];
__device__ float d_Bias[NBATCH * OCH];
__device__ float d_Aa[2 * OCH];
__device__ float d_Cc[2 * OCH];

// ---------------- helpers ----------------
__device__ __forceinline__ uint32_t smem_u32(const void* p) {
    uint32_t a;
    asm("{ .reg .u64 t; cvta.to.shared.u64 t, %1; cvt.u32.u64 %0, t; }" : "=r"(a) : "l"(p));
    return a;
}
__device__ __forceinline__ void ldsm4(uint32_t* r, uint32_t addr) {
    asm volatile("ldmatrix.sync.aligned.m8n8.x4.shared.b16 {%0,%1,%2,%3}, [%4];"
        : "=r"(r[0]), "=r"(r[1]), "=r"(r[2]), "=r"(r[3]) : "r"(addr));
}
__device__ __forceinline__ void mma16816(float* c, const uint32_t* a, const uint32_t* b) {
    asm volatile("mma.sync.aligned.m16n8k16.row.col.f32.f16.f16.f32 "
        "{%0,%1,%2,%3}, {%4,%5,%6,%7}, {%8,%9}, {%0,%1,%2,%3};"
        : "+f"(c[0]), "+f"(c[1]), "+f"(c[2]), "+f"(c[3])
        : "r"(a[0]), "r"(a[1]), "r"(a[2]), "r"(a[3]), "r"(b[0]), "r"(b[1]));
}
__device__ __forceinline__ uint32_t swz_off(int row, int kc) {
    return (uint32_t)(row * 64 + ((((kc >> 3) ^ ((row >> 1) & 3)) << 4)) + (kc & 7) * 2);
}
__device__ __forceinline__ float leaky(float v) { return fmaxf(v, SLOPE * v); }

// ---------------- prep: fold weights to fp16 ----------------
__global__ void prep_w(const float* __restrict__ W, int Cin)
{
    int Kw = 2 * Cin + 3;
    int idx = blockIdx.x * blockDim.x + threadIdx.x;
    if (idx < OCH * 192) {
        int o = idx / 192, c = idx % 192;
        float v = 0.f;
        if (c < Cin)          v = W[o * Kw + c] + W[o * Kw + Cin + c];
        else if (c < Cin + 3) v = W[o * Kw + 2 * Cin + (c - Cin)];
        d_Whi[idx] = __float2half_rn(v);
    }
}

// ---------------- prep: per-batch x0 bias (fp32 exact) ----------------
__global__ void prep_bias(const float* __restrict__ W, int Cin,
                          const float* __restrict__ X,
                          const float* __restrict__ aP, const float* __restrict__ cP)
{
    __shared__ float x0[OCH];
    int b = blockIdx.x, o = threadIdx.x;
    if (o < Cin) {
        float x = X[(size_t)b * Cin * GPTS + (size_t)o * GPTS];
        if (aP) x = leaky(fmaf(aP[o], x, cP[o]));
        x0[o] = x;
    }
    __syncthreads();
    int Kw = 2 * Cin + 3;
    float acc = 0.f;
    for (int c = 0; c < Cin; c++) acc = fmaf(W[o * Kw + Cin + c], x0[c], acc);
    d_Bias[b * OCH + o] = acc;
}

// ---------------- HMMA GEMM layer (2-term split: hh + hl) ----------------
__global__ void __launch_bounds__(256, 2)
gemm_mm(const float* __restrict__ X, int Cin, int nsec,
        const float* __restrict__ ev,
        const float* __restrict__ aP, const float* __restrict__ cP,
        float* __restrict__ Y)
{
    extern __shared__ __align__(16) char smem[];
    uint32_t sb = smem_u32(smem);

    const int tid = threadIdx.x, lane = tid & 31, wid = tid >> 5;
    const int wm = wid >> 2, wn = wid & 3;
    const int gt = blockIdx.x, b = blockIdx.y;
    const int g0 = gt * TN;
    const int ctaIdx = b * NTILE + gt;
    const bool useAff = (aP != nullptr);

    float* afp = (float*)(smem + SMB_AF);
    if (tid < OCH) { afp[tid] = useAff ? aP[tid] : 1.f; afp[OCH + tid] = useAff ? cP[tid] : 0.f; }
    __syncthreads();

    const float* xb  = X  + (size_t)b * Cin * GPTS + g0;
    const float* evb = ev + (size_t)b * 3   * GPTS + g0;
    const uint32_t* Wh32 = (const uint32_t*)d_Whi;

    const int lg = tid & 127, chh = tid >> 7;

    float xr[16];

    float c[4][4][4];
#pragma unroll
    for (int mi = 0; mi < 4; mi++)
#pragma unroll
        for (int ni = 0; ni < 4; ni++)
#pragma unroll
            for (int e = 0; e < 4; e++) c[mi][ni][e] = 0.f;

    auto ldgX = [&](int s) {
#pragma unroll
        for (int j = 0; j < 16; j++) {
            int ch = s * KSEC + chh * 16 + j;
            float v = 0.f;
            if (ch < Cin)            v = xb[(size_t)ch * GPTS + lg];
            else if (ch < Cin + 3)   v = evb[(size_t)(ch - Cin) * GPTS + lg];
            xr[j] = v;
        }
    };
    auto stsX = [&](int s, int buf) {
        uint32_t XhO = SMB_BUF + buf * 24576 + 8192;
        uint32_t XlO = XhO + 8192;
#pragma unroll
        for (int j2 = 0; j2 < 8; j2++) {
            int kc = chh * 16 + j2 * 2;
            int ch0 = s * KSEC + kc;
            float v0 = xr[j2 * 2], v1 = xr[j2 * 2 + 1];
            if (useAff) {
                if (ch0 < Cin)     v0 = leaky(fmaf(afp[ch0], v0, afp[OCH + ch0]));
                if (ch0 + 1 < Cin) v1 = leaky(fmaf(afp[ch0 + 1], v1, afp[OCH + ch0 + 1]));
            }
            __half h0 = __float2half_rn(v0), h1 = __float2half_rn(v1);
            __half l0 = __float2half_rn(v0 - __half2float(h0));
            __half l1 = __float2half_rn(v1 - __half2float(h1));
            __half2 hp = __halves2half2(h0, h1), lp = __halves2half2(l0, l1);
            uint32_t off = swz_off(lg, kc);
            *(uint32_t*)(smem + XhO + off) = *(uint32_t*)&hp;
            *(uint32_t*)(smem + XlO + off) = *(uint32_t*)&lp;
        }
    };
    auto stsW = [&](int s, int buf) {
        uint32_t WhO = SMB_BUF + buf * 24576;
#pragma unroll
        for (int i = 0; i < 8; i++) {
            int idx = tid + i * 256;
            int o = idx >> 4, kp = idx & 15;
            uint32_t vh = Wh32[o * 96 + s * 16 + kp];
            uint32_t off = swz_off(o, kp * 2);
            *(uint32_t*)(smem + WhO + off) = vh;
        }
    };

    // prologue
    ldgX(0);
    stsX(0, 0);
    stsW(0, 0);

    for (int s = 0; s < nsec; s++) {
        int buf = s & 1;
        __syncthreads();
        if (s + 1 < nsec) ldgX(s + 1);

        uint32_t WhB = sb + SMB_BUF + buf * 24576;
        uint32_t XhB = WhB + 8192;
        uint32_t XlB = WhB + 16384;
#pragma unroll
        for (int ks = 0; ks < 2; ks++) {
            uint32_t ah[4][4], bh[4][2], bl[4][2];
#pragma unroll
            for (int mi = 0; mi < 4; mi++) {
                int row = wm * 64 + mi * 16 + (lane & 15);
                int chunk = 2 * ks + (lane >> 4);
                uint32_t off = (uint32_t)(row * 64 + (((chunk ^ ((row >> 1) & 3)) << 4)));
                ldsm4(ah[mi], WhB + off);
            }
#pragma unroll
            for (int p = 0; p < 2; p++) {
                int row = wn * 32 + p * 16 + (lane & 7) + ((lane >> 4) << 3);
                int chunk = 2 * ks + ((lane >> 3) & 1);
                uint32_t off = (uint32_t)(row * 64 + (((chunk ^ ((row >> 1) & 3)) << 4)));
                uint32_t t[4];
                ldsm4(t, XhB + off);
                bh[2 * p][0] = t[0]; bh[2 * p][1] = t[1];
                bh[2 * p + 1][0] = t[2]; bh[2 * p + 1][1] = t[3];
                ldsm4(t, XlB + off);
                bl[2 * p][0] = t[0]; bl[2 * p][1] = t[1];
                bl[2 * p + 1][0] = t[2]; bl[2 * p + 1][1] = t[3];
            }
#pragma unroll
            for (int mi = 0; mi < 4; mi++)
#pragma unroll
                for (int ni = 0; ni < 4; ni++) mma16816(c[mi][ni], ah[mi], bh[ni]);
#pragma unroll
            for (int mi = 0; mi < 4; mi++)
#pragma unroll
                for (int ni = 0; ni < 4; ni++) mma16816(c[mi][ni], ah[mi], bl[ni]);
        }

        if (s + 1 < nsec) {
            stsX(s + 1, buf ^ 1);
            stsW(s + 1, buf ^ 1);
        }
    }
    __syncthreads();

    // ---------------- epilogue ----------------
    float* Ysm = (float*)(smem + SMB_YS);
#pragma unroll
    for (int mi = 0; mi < 4; mi++)
#pragma unroll
        for (int ni = 0; ni < 4; ni++) {
            int r0 = wm * 64 + mi * 16 + (lane >> 2);
            int cc = wn * 32 + ni * 8 + 2 * (lane & 3);
            Ysm[r0 * 132 + cc]           = c[mi][ni][0];
            Ysm[r0 * 132 + cc + 1]       = c[mi][ni][1];
            Ysm[(r0 + 8) * 132 + cc]     = c[mi][ni][2];
            Ysm[(r0 + 8) * 132 + cc + 1] = c[mi][ni][3];
        }
    __syncthreads();

    int o = tid >> 1, hc = tid & 1;
    float bias = d_Bias[b * OCH + o];
    float s1 = 0.f, s2 = 0.f;
    float* yrow = Y + ((size_t)b * OCH + o) * GPTS + g0 + hc * 64;
    const float* yr = &Ysm[o * 132 + hc * 64];
#pragma unroll
    for (int j = 0; j < 64; j += 4) {
        float4 v;
        v.x = yr[j]     - bias;
        v.y = yr[j + 1] - bias;
        v.z = yr[j + 2] - bias;
        v.w = yr[j + 3] - bias;
        s1 += (v.x + v.y) + (v.z + v.w);
        s2 += (v.x * v.x + v.y * v.y) + (v.z * v.z + v.w * v.w);
        *(float4*)(yrow + j) = v;
    }
    float* st = (float*)(smem + SMB_ST);
    st[o * 2 + hc] = s1;
    st[256 + o * 2 + hc] = s2;
    __syncthreads();
    if (tid < OCH) {
        d_Psum[(size_t)tid * NB + ctaIdx] = st[tid * 2] + st[tid * 2 + 1];
        d_Psq [(size_t)tid * NB + ctaIdx] = st[256 + tid * 2] + st[256 + tid * 2 + 1];
    }
}

// ---------------- stats (1024 threads) ----------------
__global__ void stats_kernel(const float* __restrict__ gamma,
                             const float* __restrict__ beta,
                             float* __restrict__ aOut, float* __restrict__ cOut)
{
    int o = blockIdx.x, tid = threadIdx.x;
    float s = 0.f, q = 0.f;
    for (int i = tid; i < NB; i += 1024) {
        s += d_Psum[(size_t)o * NB + i];
        q += d_Psq [(size_t)o * NB + i];
    }
    __shared__ float ss[1024], sq[1024];
    ss[tid] = s; sq[tid] = q;
    __syncthreads();
    for (int st = 512; st > 0; st >>= 1) {
        if (tid < st) { ss[tid] += ss[tid + st]; sq[tid] += sq[tid + st]; }
        __syncthreads();
    }
    if (tid == 0) {
        float N = (float)((size_t)NBATCH * GPTS);
        float m = ss[0] / N;
        float v = sq[0] / N - m * m;
        float inv = rsqrtf(v + EPSV);
        float a = gamma[o] * inv;
        aOut[o] = a;
        cOut[o] = beta[o] - a * m;
    }
}

// ---------------- final: BN + leaky + max over G ----------------
__global__ void final_kernel(const float* __restrict__ Y,
                             const float* __restrict__ a,
                             const float* __restrict__ c,
                             float* __restrict__ out)
{
    int row = blockIdx.x;
    int o = row & 127;
    int tid = threadIdx.x;
    float av = a[o], cv = c[o];
    float m = -3.4e38f;
    const float* p = Y + (size_t)row * GPTS;
    for (int g = tid; g < GPTS; g += 256) {
        float v = fmaf(av, p[g], cv);
        m = fmaxf(m, leaky(v));
    }
    __shared__ float smx[256];
    smx[tid] = m;
    __syncthreads();
    for (int st = 128; st > 0; st >>= 1) {
        if (tid < st) smx[tid] = fmaxf(smx[tid], smx[tid + st]);
        __syncthreads();
    }
    if (tid == 0) out[row] = smx[0];
}

// ---------------- launcher ----------------
extern "C" void kernel_launch(void* const* d_in, const int* in_sizes, int n_in,
                              void* d_out, int out_size)
{
    const float* feat = (const float*)d_in[0];
    const float* ev   = (const float*)d_in[1];
    const float* W[4] = {(const float*)d_in[2], (const float*)d_in[3],
                         (const float*)d_in[4], (const float*)d_in[5]};
    const float* gm[4] = {(const float*)d_in[6],  (const float*)d_in[8],
                          (const float*)d_in[10], (const float*)d_in[12]};
    const float* bt[4] = {(const float*)d_in[7],  (const float*)d_in[9],
                          (const float*)d_in[11], (const float*)d_in[13]};
    float* out = (float*)d_out;

    cudaFuncSetAttribute(gemm_mm, cudaFuncAttributeMaxDynamicSharedMemorySize, SMB_DYN);

    float *y0, *y1, *aa, *cc;
    cudaGetSymbolAddress((void**)&y0, d_Y0);
    cudaGetSymbolAddress((void**)&y1, d_Y1);
    cudaGetSymbolAddress((void**)&aa, d_Aa);
    cudaGetSymbolAddress((void**)&cc, d_Cc);

    float* ybuf[2] = {y0, y1};
    const float* cur = feat;
    int curC = 64;
    float* aPrev = nullptr;
    float* cPrev = nullptr;

    dim3 gg(NTILE, NBATCH);
    for (int L = 0; L < 4; L++) {
        int dst = L & 1;
        float* aCur = aa + dst * OCH;
        float* cCur = cc + dst * OCH;
        int nsec = (curC + 3 + KSEC - 1) / KSEC;      // 64->3, 128->5
        prep_w<<<(OCH * 192 + 255) / 256, 256>>>(W[L], curC);
        prep_bias<<<NBATCH, OCH>>>(W[L], curC, cur, aPrev, cPrev);
        gemm_mm<<<gg, 256, SMB_DYN>>>(cur, curC, nsec, ev, aPrev, cPrev, ybuf[dst]);
        stats_kernel<<<OCH, 1024>>>(gm[L], bt[L], aCur, cCur);
        cur = ybuf[dst];
        curC = OCH;
        aPrev = aCur;
        cPrev = cCur;
    }
    final_kernel<<<NBATCH * OCH, 256>>>(cur, aPrev, cPrev, out);
}

// round 6
// speedup vs baseline: 2.4569x; 1.2552x over previous
#include <cuda_runtime.h>
#include <cuda_fp16.h>
#include <cstdint>
#include <cstddef>

#define GPTS   8192
#define NBATCH 32
#define OCH    128
#define TN     128
#define NTILE  (GPTS / TN)          // 64 g-tiles
#define NB     (NBATCH * NTILE)     // 2048 CTAs per layer
#define KSEC   32
#define EPSV   1e-5f
#define SLOPE  0.1f

// SMEM byte offsets (dynamic)
// buffer: [Wh 8K | Xh 8K | Xl 8K] = 24KB, x2 buffers = 48KB
#define SMB_BUF    0
#define SMB_AF     49152    // affine a[128], c[128]
#define SMB_BIAS   50176    // bias[128]
#define SMB_SUM    50688    // sSum[128][4] + sSqr[128][4] = 4KB
#define SMB_DYN    55296

// ---------------- device scratch ----------------
__device__ float d_Y0[(size_t)NBATCH * OCH * GPTS];
__device__ float d_Y1[(size_t)NBATCH * OCH * GPTS];
__device__ float d_Psum[(size_t)OCH * NB];
__device__ float d_Psq [(size_t)OCH * NB];
__device__ __half d_Whi[OCH * 192];
__device__ float d_Bias[NBATCH * OCH];
__device__ float d_Aa[2 * OCH];
__device__ float d_Cc[2 * OCH];

// ---------------- helpers ----------------
__device__ __forceinline__ uint32_t smem_u32(const void* p) {
    uint32_t a;
    asm("{ .reg .u64 t; cvta.to.shared.u64 t, %1; cvt.u32.u64 %0, t; }" : "=r"(a) : "l"(p));
    return a;
}
__device__ __forceinline__ void ldsm4(uint32_t* r, uint32_t addr) {
    asm volatile("ldmatrix.sync.aligned.m8n8.x4.shared.b16 {%0,%1,%2,%3}, [%4];"
        : "=r"(r[0]), "=r"(r[1]), "=r"(r[2]), "=r"(r[3]) : "r"(addr));
}
__device__ __forceinline__ void mma16816(float* c, const uint32_t* a, const uint32_t* b) {
    asm volatile("mma.sync.aligned.m16n8k16.row.col.f32.f16.f16.f32 "
        "{%0,%1,%2,%3}, {%4,%5,%6,%7}, {%8,%9}, {%0,%1,%2,%3};"
        : "+f"(c[0]), "+f"(c[1]), "+f"(c[2]), "+f"(c[3])
        : "r"(a[0]), "r"(a[1]), "r"(a[2]), "r"(a[3]), "r"(b[0]), "r"(b[1]));
}
__device__ __forceinline__ uint32_t swz_off(int row, int kc) {
    return (uint32_t)(row * 64 + ((((kc >> 3) ^ ((row >> 1) & 3)) << 4)) + (kc & 7) * 2);
}
__device__ __forceinline__ float leaky(float v) { return fmaxf(v, SLOPE * v); }

// ---------------- prep: fold weights to fp16 ----------------
__global__ void prep_w(const float* __restrict__ W, int Cin)
{
    int Kw = 2 * Cin + 3;
    int idx = blockIdx.x * blockDim.x + threadIdx.x;
    if (idx < OCH * 192) {
        int o = idx / 192, c = idx % 192;
        float v = 0.f;
        if (c < Cin)          v = W[o * Kw + c] + W[o * Kw + Cin + c];
        else if (c < Cin + 3) v = W[o * Kw + 2 * Cin + (c - Cin)];
        d_Whi[idx] = __float2half_rn(v);
    }
}

// ---------------- prep: per-batch x0 bias (fp32 exact) ----------------
__global__ void prep_bias(const float* __restrict__ W, int Cin,
                          const float* __restrict__ X,
                          const float* __restrict__ aP, const float* __restrict__ cP)
{
    __shared__ float x0[OCH];
    int b = blockIdx.x, o = threadIdx.x;
    if (o < Cin) {
        float x = X[(size_t)b * Cin * GPTS + (size_t)o * GPTS];
        if (aP) x = leaky(fmaf(aP[o], x, cP[o]));
        x0[o] = x;
    }
    __syncthreads();
    int Kw = 2 * Cin + 3;
    float acc = 0.f;
    for (int c = 0; c < Cin; c++) acc = fmaf(W[o * Kw + Cin + c], x0[c], acc);
    d_Bias[b * OCH + o] = acc;
}

// ---------------- HMMA GEMM layer (2-term split: hh + hl) ----------------
__global__ void __launch_bounds__(256, 2)
gemm_mm(const float* __restrict__ X, int Cin, int nsec,
        const float* __restrict__ ev,
        const float* __restrict__ aP, const float* __restrict__ cP,
        float* __restrict__ Y)
{
    extern __shared__ __align__(16) char smem[];
    uint32_t sb = smem_u32(smem);

    const int tid = threadIdx.x, lane = tid & 31, wid = tid >> 5;
    const int wm = wid >> 2, wn = wid & 3;
    const int gt = blockIdx.x, b = blockIdx.y;
    const int g0 = gt * TN;
    const int ctaIdx = b * NTILE + gt;
    const bool useAff = (aP != nullptr);

    float* afp = (float*)(smem + SMB_AF);
    float* sB  = (float*)(smem + SMB_BIAS);
    if (tid < OCH) {
        afp[tid] = useAff ? aP[tid] : 1.f;
        afp[OCH + tid] = useAff ? cP[tid] : 0.f;
        sB[tid] = d_Bias[b * OCH + tid];
    }
    __syncthreads();

    const float* xb  = X  + (size_t)b * Cin * GPTS + g0;
    const float* evb = ev + (size_t)b * 3   * GPTS + g0;
    const uint32_t* Wh32 = (const uint32_t*)d_Whi;

    const int lg = tid & 127, chh = tid >> 7;

    float xr[16];

    float c[4][4][4];
#pragma unroll
    for (int mi = 0; mi < 4; mi++)
#pragma unroll
        for (int ni = 0; ni < 4; ni++)
#pragma unroll
            for (int e = 0; e < 4; e++) c[mi][ni][e] = 0.f;

    auto ldgX = [&](int s) {
#pragma unroll
        for (int j = 0; j < 16; j++) {
            int ch = s * KSEC + chh * 16 + j;
            float v = 0.f;
            if (ch < Cin)            v = xb[(size_t)ch * GPTS + lg];
            else if (ch < Cin + 3)   v = evb[(size_t)(ch - Cin) * GPTS + lg];
            xr[j] = v;
        }
    };
    // conflict-free STS.128: per thread 2 chunk-groups of 8 halves, h and l planes
    auto stsX = [&](int s, int buf) {
        uint32_t XhO = SMB_BUF + buf * 24576 + 8192;
        uint32_t XlO = XhO + 8192;
#pragma unroll
        for (int j = 0; j < 16; j++) {
            int ch = s * KSEC + chh * 16 + j;
            if (useAff && ch < Cin) xr[j] = leaky(fmaf(afp[ch], xr[j], afp[OCH + ch]));
        }
#pragma unroll
        for (int grp = 0; grp < 2; grp++) {
            uint32_t hq[4], lq[4];
#pragma unroll
            for (int q = 0; q < 4; q++) {
                float v0 = xr[grp * 8 + 2 * q], v1 = xr[grp * 8 + 2 * q + 1];
                __half h0 = __float2half_rn(v0), h1 = __float2half_rn(v1);
                __half l0 = __float2half_rn(v0 - __half2float(h0));
                __half l1 = __float2half_rn(v1 - __half2float(h1));
                __half2 hp = __halves2half2(h0, h1), lp = __halves2half2(l0, l1);
                hq[q] = *(uint32_t*)&hp;
                lq[q] = *(uint32_t*)&lp;
            }
            int kcg = chh * 2 + grp;
            uint32_t off = (uint32_t)(lg * 64 + (((kcg ^ ((lg >> 1) & 3)) << 4)));
            *(uint4*)(smem + XhO + off) = make_uint4(hq[0], hq[1], hq[2], hq[3]);
            *(uint4*)(smem + XlO + off) = make_uint4(lq[0], lq[1], lq[2], lq[3]);
        }
    };
    auto stsW = [&](int s, int buf) {
        uint32_t WhO = SMB_BUF + buf * 24576;
#pragma unroll
        for (int i = 0; i < 8; i++) {
            int idx = tid + i * 256;
            int o = idx >> 4, kp = idx & 15;
            uint32_t vh = Wh32[o * 96 + s * 16 + kp];
            uint32_t off = swz_off(o, kp * 2);
            *(uint32_t*)(smem + WhO + off) = vh;
        }
    };

    // prologue
    ldgX(0);
    stsX(0, 0);
    stsW(0, 0);

    for (int s = 0; s < nsec; s++) {
        int buf = s & 1;
        __syncthreads();
        if (s + 1 < nsec) ldgX(s + 1);

        uint32_t WhB = sb + SMB_BUF + buf * 24576;
        uint32_t XhB = WhB + 8192;
        uint32_t XlB = WhB + 16384;
#pragma unroll
        for (int ks = 0; ks < 2; ks++) {
            uint32_t ah[4][4], bh[4][2], bl[4][2];
#pragma unroll
            for (int mi = 0; mi < 4; mi++) {
                int row = wm * 64 + mi * 16 + (lane & 15);
                int chunk = 2 * ks + (lane >> 4);
                uint32_t off = (uint32_t)(row * 64 + (((chunk ^ ((row >> 1) & 3)) << 4)));
                ldsm4(ah[mi], WhB + off);
            }
#pragma unroll
            for (int p = 0; p < 2; p++) {
                int row = wn * 32 + p * 16 + (lane & 7) + ((lane >> 4) << 3);
                int chunk = 2 * ks + ((lane >> 3) & 1);
                uint32_t off = (uint32_t)(row * 64 + (((chunk ^ ((row >> 1) & 3)) << 4)));
                uint32_t t[4];
                ldsm4(t, XhB + off);
                bh[2 * p][0] = t[0]; bh[2 * p][1] = t[1];
                bh[2 * p + 1][0] = t[2]; bh[2 * p + 1][1] = t[3];
                ldsm4(t, XlB + off);
                bl[2 * p][0] = t[0]; bl[2 * p][1] = t[1];
                bl[2 * p + 1][0] = t[2]; bl[2 * p + 1][1] = t[3];
            }
#pragma unroll
            for (int mi = 0; mi < 4; mi++)
#pragma unroll
                for (int ni = 0; ni < 4; ni++) mma16816(c[mi][ni], ah[mi], bh[ni]);
#pragma unroll
            for (int mi = 0; mi < 4; mi++)
#pragma unroll
                for (int ni = 0; ni < 4; ni++) mma16816(c[mi][ni], ah[mi], bl[ni]);
        }

        if (s + 1 < nsec) {
            stsX(s + 1, buf ^ 1);
            stsW(s + 1, buf ^ 1);
        }
    }

    // ---------------- register-direct epilogue ----------------
    float* sSum = (float*)(smem + SMB_SUM);   // [128][4]
    float* sSqr = sSum + 512;
    float* Yb = Y + (size_t)b * OCH * GPTS + g0;

#pragma unroll
    for (int mi = 0; mi < 4; mi++) {
        int r0 = wm * 64 + mi * 16 + (lane >> 2);
        float b0 = sB[r0], b1 = sB[r0 + 8];
        float s0 = 0.f, q0 = 0.f, s1 = 0.f, q1 = 0.f;
#pragma unroll
        for (int ni = 0; ni < 4; ni++) {
            float v0 = c[mi][ni][0] - b0;
            float v1 = c[mi][ni][1] - b0;
            float v2 = c[mi][ni][2] - b1;
            float v3 = c[mi][ni][3] - b1;
            s0 += v0 + v1; q0 += v0 * v0 + v1 * v1;
            s1 += v2 + v3; q1 += v2 * v2 + v3 * v3;
            int col = wn * 32 + ni * 8 + 2 * (lane & 3);
            *(float2*)(Yb + (size_t)r0 * GPTS + col)       = make_float2(v0, v1);
            *(float2*)(Yb + (size_t)(r0 + 8) * GPTS + col) = make_float2(v2, v3);
        }
        s0 += __shfl_xor_sync(0xFFFFFFFFu, s0, 1); s0 += __shfl_xor_sync(0xFFFFFFFFu, s0, 2);
        q0 += __shfl_xor_sync(0xFFFFFFFFu, q0, 1); q0 += __shfl_xor_sync(0xFFFFFFFFu, q0, 2);
        s1 += __shfl_xor_sync(0xFFFFFFFFu, s1, 1); s1 += __shfl_xor_sync(0xFFFFFFFFu, s1, 2);
        q1 += __shfl_xor_sync(0xFFFFFFFFu, q1, 1); q1 += __shfl_xor_sync(0xFFFFFFFFu, q1, 2);
        if ((lane & 3) == 0) {
            sSum[r0 * 4 + wn] = s0;       sSqr[r0 * 4 + wn] = q0;
            sSum[(r0 + 8) * 4 + wn] = s1; sSqr[(r0 + 8) * 4 + wn] = q1;
        }
    }
    __syncthreads();
    if (tid < OCH) {
        float s = (sSum[tid * 4] + sSum[tid * 4 + 1]) + (sSum[tid * 4 + 2] + sSum[tid * 4 + 3]);
        float q = (sSqr[tid * 4] + sSqr[tid * 4 + 1]) + (sSqr[tid * 4 + 2] + sSqr[tid * 4 + 3]);
        d_Psum[(size_t)tid * NB + ctaIdx] = s;
        d_Psq [(size_t)tid * NB + ctaIdx] = q;
    }
}

// ---------------- stats (1024 threads) ----------------
__global__ void stats_kernel(const float* __restrict__ gamma,
                             const float* __restrict__ beta,
                             float* __restrict__ aOut, float* __restrict__ cOut)
{
    int o = blockIdx.x, tid = threadIdx.x;
    float s = 0.f, q = 0.f;
    for (int i = tid; i < NB; i += 1024) {
        s += d_Psum[(size_t)o * NB + i];
        q += d_Psq [(size_t)o * NB + i];
    }
    __shared__ float ss[1024], sq[1024];
    ss[tid] = s; sq[tid] = q;
    __syncthreads();
    for (int st = 512; st > 0; st >>= 1) {
        if (tid < st) { ss[tid] += ss[tid + st]; sq[tid] += sq[tid + st]; }
        __syncthreads();
    }
    if (tid == 0) {
        float N = (float)((size_t)NBATCH * GPTS);
        float m = ss[0] / N;
        float v = sq[0] / N - m * m;
        float inv = rsqrtf(v + EPSV);
        float a = gamma[o] * inv;
        aOut[o] = a;
        cOut[o] = beta[o] - a * m;
    }
}

// ---------------- final: BN + leaky + max over G ----------------
__global__ void final_kernel(const float* __restrict__ Y,
                             const float* __restrict__ a,
                             const float* __restrict__ c,
                             float* __restrict__ out)
{
    int row = blockIdx.x;
    int o = row & 127;
    int tid = threadIdx.x;
    float av = a[o], cv = c[o];
    float m = -3.4e38f;
    const float4* p = (const float4*)(Y + (size_t)row * GPTS);
    for (int g = tid; g < GPTS / 4; g += 256) {
        float4 x = p[g];
        m = fmaxf(m, leaky(fmaf(av, x.x, cv)));
        m = fmaxf(m, leaky(fmaf(av, x.y, cv)));
        m = fmaxf(m, leaky(fmaf(av, x.z, cv)));
        m = fmaxf(m, leaky(fmaf(av, x.w, cv)));
    }
    __shared__ float smx[256];
    smx[tid] = m;
    __syncthreads();
    for (int st = 128; st > 0; st >>= 1) {
        if (tid < st) smx[tid] = fmaxf(smx[tid], smx[tid + st]);
        __syncthreads();
    }
    if (tid == 0) out[row] = smx[0];
}

// ---------------- launcher ----------------
extern "C" void kernel_launch(void* const* d_in, const int* in_sizes, int n_in,
                              void* d_out, int out_size)
{
    const float* feat = (const float*)d_in[0];
    const float* ev   = (const float*)d_in[1];
    const float* W[4] = {(const float*)d_in[2], (const float*)d_in[3],
                         (const float*)d_in[4], (const float*)d_in[5]};
    const float* gm[4] = {(const float*)d_in[6],  (const float*)d_in[8],
                          (const float*)d_in[10], (const float*)d_in[12]};
    const float* bt[4] = {(const float*)d_in[7],  (const float*)d_in[9],
                          (const float*)d_in[11], (const float*)d_in[13]};
    float* out = (float*)d_out;

    cudaFuncSetAttribute(gemm_mm, cudaFuncAttributeMaxDynamicSharedMemorySize, SMB_DYN);

    float *y0, *y1, *aa, *cc;
    cudaGetSymbolAddress((void**)&y0, d_Y0);
    cudaGetSymbolAddress((void**)&y1, d_Y1);
    cudaGetSymbolAddress((void**)&aa, d_Aa);
    cudaGetSymbolAddress((void**)&cc, d_Cc);

    float* ybuf[2] = {y0, y1};
    const float* cur = feat;
    int curC = 64;
    float* aPrev = nullptr;
    float* cPrev = nullptr;

    dim3 gg(NTILE, NBATCH);
    for (int L = 0; L < 4; L++) {
        int dst = L & 1;
        float* aCur = aa + dst * OCH;
        float* cCur = cc + dst * OCH;
        int nsec = (curC + 3 + KSEC - 1) / KSEC;      // 64->3, 128->5
        prep_w<<<(OCH * 192 + 255) / 256, 256>>>(W[L], curC);
        prep_bias<<<NBATCH, OCH>>>(W[L], curC, cur, aPrev, cPrev);
        gemm_mm<<<gg, 256, SMB_DYN>>>(cur, curC, nsec, ev, aPrev, cPrev, ybuf[dst]);
        stats_kernel<<<OCH, 1024>>>(gm[L], bt[L], aCur, cCur);
        cur = ybuf[dst];
        curC = OCH;
        aPrev = aCur;
        cPrev = cCur;
    }
    final_kernel<<<NBATCH * OCH, 256>>>(cur, aPrev, cPrev, out);
}